// round 9
// baseline (speedup 1.0000x reference)
#include <cuda_runtime.h>
#include <cuda_fp16.h>
#include <cstdint>

// ---------------------------------------------------------------------------
// GRU via mma.sync (HMMA). 128 CTAs x 512 thr (16 warps), 32 samples/CTA.
// R9: double-buffered h1/h2/x tiles -> ONE half-barrier per step;
// dependent-MMA distance raised 1 -> 3; weight streams balanced
// (whh1 + wih2 from L2, whh2 SMEM-resident). Weights fp16 hi-only;
// h and x carried as fp16 hi+lo pairs. Warp (wid&7, wid>>3) owns gate rows
// 16*(wid&7) and samples 16*(wid>>3)..+15 — all work warp-local.
// ---------------------------------------------------------------------------

#define HID  128
#define MB   32
#define LSEQ 128
#define NCLS 24
#define NTHR 512

// A-fragment arrays: [frag][lane] uint4, frag = mt*nkt + kt
__device__ uint4 g_wih1H[24 * 32], g_wih1L[24 * 32];   // K=16
__device__ uint4 g_whh1H[192 * 32];                    // streamed (L1 phase)
__device__ uint4 g_wih2H[192 * 32];                    // streamed (L2 phase)
__device__ uint4 g_whh2H[192 * 32];                    // -> SMEM resident

// SMEM byte offsets
#define S_WHH2  0        // whh2 hi frags (98304)
#define S_H1    98304    // 2 bufs x (hi 8192 + lo 8192) = 32768
#define S_H2    131072   // 32768
#define S_X     163840   // 2 bufs x (hi 1024 + lo 1024) = 4096
#define SMEM_SZ 167936

__device__ __forceinline__ uint32_t smem_u32(const void* p) {
    uint32_t a;
    asm("{ .reg .u64 t; cvta.to.shared.u64 t, %1; cvt.u32.u64 %0, t; }"
        : "=r"(a) : "l"(p));
    return a;
}
__device__ __forceinline__ void ldm2(uint32_t& r0, uint32_t& r1, uint32_t a) {
    asm volatile("ldmatrix.sync.aligned.m8n8.x2.shared.b16 {%0,%1}, [%2];"
                 : "=r"(r0), "=r"(r1) : "r"(a));
}
__device__ __forceinline__ void mmaf(float* d, const uint4& a,
                                     uint32_t b0, uint32_t b1) {
    asm volatile("mma.sync.aligned.m16n8k16.row.col.f32.f16.f16.f32 "
                 "{%0,%1,%2,%3}, {%4,%5,%6,%7}, {%8,%9}, {%0,%1,%2,%3};"
                 : "+f"(d[0]), "+f"(d[1]), "+f"(d[2]), "+f"(d[3])
                 : "r"(a.x), "r"(a.y), "r"(a.z), "r"(a.w), "r"(b0), "r"(b1));
}
__device__ __forceinline__ float sigf(float v) { return 1.f / (1.f + __expf(-v)); }
__device__ __forceinline__ float tanhf_fast(float v) {
    v = fminf(fmaxf(v, -15.f), 15.f);
    float e = __expf(2.f * v);
    return (e - 1.f) / (e + 1.f);
}

// ---- prep: pack fp32 weights into per-lane A fragments --------------------
__global__ void prep_kernel(const float* __restrict__ w_ih1,
                            const float* __restrict__ w_hh1,
                            const float* __restrict__ w_ih2,
                            const float* __restrict__ w_hh2) {
    int t = blockIdx.x * blockDim.x + threadIdx.x;
    if (t >= 600 * 32) return;
    int f = t >> 5, lane = t & 31;
    const float* W; uint4* dh; uint4* dl = nullptr; int K, fl;
    if (f < 24)       { W = w_ih1; dh = g_wih1H; dl = g_wih1L; K = 16;  fl = f; }
    else if (f < 216) { W = w_hh1; dh = g_whh1H; K = 128; fl = f - 24; }
    else if (f < 408) { W = w_ih2; dh = g_wih2H; K = 128; fl = f - 216; }
    else              { W = w_hh2; dh = g_whh2H; K = 128; fl = f - 408; }
    int nkt = K >> 4;
    int mt = fl / nkt, kt = fl % nkt;
    int gid = lane >> 2, tig = lane & 3;
    int r0 = mt * 16 + gid, r1 = r0 + 8, c0 = kt * 16 + tig * 2;
    float2 v[4];
    v[0] = *(const float2*)(W + r0 * K + c0);
    v[1] = *(const float2*)(W + r1 * K + c0);
    v[2] = *(const float2*)(W + r0 * K + c0 + 8);
    v[3] = *(const float2*)(W + r1 * K + c0 + 8);
    uint4 oh, ol;
    uint32_t* ph = (uint32_t*)&oh;
    uint32_t* pl = (uint32_t*)&ol;
#pragma unroll
    for (int q = 0; q < 4; q++) {
        __half2 hi = __floats2half2_rn(v[q].x, v[q].y);
        __half2 lo = __floats2half2_rn(v[q].x - __half2float(__low2half(hi)),
                                       v[q].y - __half2float(__high2half(hi)));
        ph[q] = *(uint32_t*)&hi;
        pl[q] = *(uint32_t*)&lo;
    }
    dh[fl * 32 + lane] = oh;
    if (dl) dl[fl * 32 + lane] = ol;
}

// ---------------------------------------------------------------------------
__global__ __launch_bounds__(NTHR, 1)
void gru_mma_kernel(const float* __restrict__ x,
                    const float* __restrict__ b_ih1, const float* __restrict__ b_hh1,
                    const float* __restrict__ b_ih2, const float* __restrict__ b_hh2,
                    const float* __restrict__ fc_w,  const float* __restrict__ fc_b,
                    float* __restrict__ out) {
    extern __shared__ char smem[];
    const uint32_t sb = smem_u32(smem);
    const int tid = threadIdx.x;
    const int wid = tid >> 5, lane = tid & 31;
    const int wpair = wid & 7;           // gate row-group (rows 16*wpair)
    const int shalf = wid >> 3;          // sample half
    const int b0 = blockIdx.x * MB;
    const int gid = lane >> 2, tig = lane & 3;
    const int lr = lane & 7, lh = (lane >> 3) & 1;
    const int xorv = lr << 4;
    const int wbase = wpair * 16;
    const int ntb = shalf * 2;           // this warp's two n-tiles
    const int barid = 1 + shalf;
    const int ht = tid & 255;

#define BARH() asm volatile("bar.sync %0, 256;" :: "r"(barid) : "memory")

    // double-buffer byte offsets (uniform per warp)
    uint32_t h1rd = S_H1 + 16384, h1wr = S_H1;
    uint32_t h2rd = S_H2 + 16384, h2wr = S_H2;
    uint32_t xrd  = S_X,          xwr  = S_X + 2048;

    // ---- init: whh2 frags -> SMEM, zero h buffers, stage x(0) ----
    {
        uint4* d2 = (uint4*)(smem + S_WHH2);
        for (int i = tid; i < 192 * 32; i += NTHR) d2[i] = g_whh2H[i];
        uint4 z4 = make_uint4(0, 0, 0, 0);
        uint4* hz = (uint4*)(smem + S_H1);
        for (int i = tid; i < 65536 / 16; i += NTHR) hz[i] = z4;
    }
    if (tid < 256) {
        int m = tid >> 3, p = tid & 7;
        const float2 v = *(const float2*)(x + (size_t)(b0 + m) * 2048 +
                                          (p >> 2) * 1024 + ((2 * p) & 7));
        __half2 hi = __floats2half2_rn(v.x, v.y);
        __half2 lo = __floats2half2_rn(v.x - __half2float(__low2half(hi)),
                                       v.y - __half2float(__high2half(hi)));
        *(__half2*)(smem + S_X + m * 32 + p * 4) = hi;
        *(__half2*)(smem + S_X + 1024 + m * 32 + p * 4) = lo;
    }
    const int j0 = wbase + gid, j1 = j0 + 8;
    float b1r[2] = { b_ih1[j0] + b_hh1[j0],             b_ih1[j1] + b_hh1[j1] };
    float b1z[2] = { b_ih1[128 + j0] + b_hh1[128 + j0], b_ih1[128 + j1] + b_hh1[128 + j1] };
    float b1i[2] = { b_ih1[256 + j0],                   b_ih1[256 + j1] };
    float b1h[2] = { b_hh1[256 + j0],                   b_hh1[256 + j1] };
    float b2r[2] = { b_ih2[j0] + b_hh2[j0],             b_ih2[j1] + b_hh2[j1] };
    float b2z[2] = { b_ih2[128 + j0] + b_hh2[128 + j0], b_ih2[128 + j1] + b_hh2[128 + j1] };
    float b2i[2] = { b_ih2[256 + j0],                   b_ih2[256 + j1] };
    float b2h[2] = { b_hh2[256 + j0],                   b_hh2[256 + j1] };

    float h1reg[8], h2reg[8];
#pragma unroll
    for (int q = 0; q < 8; q++) { h1reg[q] = 0.f; h2reg[q] = 0.f; }

    float ar[2][4], az[2][4], ai[2][4], ah[2][4];
    __syncthreads();

#define ZERO_ACC() { _Pragma("unroll") for (int n_ = 0; n_ < 2; n_++) \
    _Pragma("unroll") for (int e_ = 0; e_ < 4; e_++) { \
        ar[n_][e_] = 0.f; az[n_][e_] = 0.f; ai[n_][e_] = 0.f; ah[n_][e_] = 0.f; } }

// epilogue: gate math + h update + hi/lo store to hwr_ (warp-local)
#define EPILOGUE(br_, bz_, bi_, bh_, hreg_, hwr_) { \
    _Pragma("unroll") for (int ntl = 0; ntl < 2; ntl++) { \
        int nt_ = ntb + ntl; \
        _Pragma("unroll") for (int e_ = 0; e_ < 4; e_++) { \
            int rowi_ = e_ >> 1; \
            int m_ = nt_ * 8 + tig * 2 + (e_ & 1); \
            float r_ = sigf(ar[ntl][e_] + br_[rowi_]); \
            float z_ = sigf(az[ntl][e_] + bz_[rowi_]); \
            float n_ = tanhf_fast(ai[ntl][e_] + bi_[rowi_] + r_ * (ah[ntl][e_] + bh_[rowi_])); \
            int idx_ = ntl * 4 + e_; \
            float h_ = n_ + z_ * (hreg_[idx_] - n_); \
            hreg_[idx_] = h_; \
            __half hhi_ = __float2half_rn(h_); \
            __half hlo_ = __float2half_rn(h_ - __half2float(hhi_)); \
            int j_ = wbase + gid + rowi_ * 8; \
            uint32_t off_ = (hwr_) + m_ * 256 + ((2 * j_) ^ ((m_ & 7) << 4)); \
            *(__half*)(smem + off_) = hhi_; \
            *(__half*)(smem + off_ + 8192) = hlo_; \
        } } }

    const uint4* wf2 = (const uint4*)(smem + S_WHH2);

#pragma unroll 1
    for (int t = 0; t < LSEQ; t++) {
        ZERO_ACC();
        // ---- L1: x contribution (K=16: Whi*xhi, Whi*xlo, Wlo*xhi) ----
        {
            uint4 Ar = g_wih1H[wpair * 32 + lane];
            uint4 Az = g_wih1H[(8 + wpair) * 32 + lane];
            uint4 Ai = g_wih1H[(16 + wpair) * 32 + lane];
            uint4 Lr = g_wih1L[wpair * 32 + lane];
            uint4 Lz = g_wih1L[(8 + wpair) * 32 + lane];
            uint4 Li = g_wih1L[(16 + wpair) * 32 + lane];
#pragma unroll
            for (int ntl = 0; ntl < 2; ntl++) {
                int nt = ntb + ntl;
                uint32_t a = sb + xrd + (nt * 8 + lr) * 32 + lh * 16;
                uint32_t bh0, bh1, bl0, bl1;
                ldm2(bh0, bh1, a);
                ldm2(bl0, bl1, a + 1024);
                // distance-3 ordering
                mmaf(ar[ntl], Ar, bh0, bh1); mmaf(az[ntl], Az, bh0, bh1); mmaf(ai[ntl], Ai, bh0, bh1);
                mmaf(ar[ntl], Ar, bl0, bl1); mmaf(az[ntl], Az, bl0, bl1); mmaf(ai[ntl], Ai, bl0, bl1);
                mmaf(ar[ntl], Lr, bh0, bh1); mmaf(az[ntl], Lz, bh0, bh1); mmaf(ai[ntl], Li, bh0, bh1);
            }
        }
        // ---- L1: whh1 @ h1(t-1) (frags streamed from L2; B from h1rd) ----
#pragma unroll 2
        for (int kt = 0; kt < 8; kt++) {
            uint4 Ar = g_whh1H[(wpair * 8 + kt) * 32 + lane];
            uint4 Az = g_whh1H[((8 + wpair) * 8 + kt) * 32 + lane];
            uint4 An = g_whh1H[((16 + wpair) * 8 + kt) * 32 + lane];
            uint32_t kb = (uint32_t)((kt * 32 + lh * 16) ^ xorv);
#pragma unroll
            for (int ntl = 0; ntl < 2; ntl++) {
                int nt = ntb + ntl;
                uint32_t a = sb + h1rd + (nt * 8 + lr) * 256 + kb;
                uint32_t bh0, bh1, bl0, bl1;
                ldm2(bh0, bh1, a);
                ldm2(bl0, bl1, a + 8192);
                mmaf(ar[ntl], Ar, bh0, bh1); mmaf(az[ntl], Az, bh0, bh1); mmaf(ah[ntl], An, bh0, bh1);
                mmaf(ar[ntl], Ar, bl0, bl1); mmaf(az[ntl], Az, bl0, bl1); mmaf(ah[ntl], An, bl0, bl1);
            }
        }
        EPILOGUE(b1r, b1z, b1i, b1h, h1reg, h1wr);
        if (ht < 128 && t + 1 < LSEQ) {        // stage x(t+1) -> xwr (own half)
            int m = shalf * 16 + (ht >> 3), p = ht & 7;
            const float2 v = *(const float2*)(x + (size_t)(b0 + m) * 2048 +
                                              (p >> 2) * 1024 + (t + 1) * 8 + ((2 * p) & 7));
            __half2 hi = __floats2half2_rn(v.x, v.y);
            __half2 lo = __floats2half2_rn(v.x - __half2float(__low2half(hi)),
                                           v.y - __half2float(__high2half(hi)));
            *(__half2*)(smem + xwr + m * 32 + p * 4) = hi;
            *(__half2*)(smem + xwr + 1024 + m * 32 + p * 4) = lo;
        }
        BARH();   // the ONE barrier: h1(t) visible; everything else covered by parity

        // ---- L2 ----
        ZERO_ACC();
        // wih2 @ h1(t) (frags streamed from L2; B from h1wr)
#pragma unroll 2
        for (int kt = 0; kt < 8; kt++) {
            uint4 Ar = g_wih2H[(wpair * 8 + kt) * 32 + lane];
            uint4 Az = g_wih2H[((8 + wpair) * 8 + kt) * 32 + lane];
            uint4 Ai = g_wih2H[((16 + wpair) * 8 + kt) * 32 + lane];
            uint32_t kb = (uint32_t)((kt * 32 + lh * 16) ^ xorv);
#pragma unroll
            for (int ntl = 0; ntl < 2; ntl++) {
                int nt = ntb + ntl;
                uint32_t a = sb + h1wr + (nt * 8 + lr) * 256 + kb;
                uint32_t bh0, bh1, bl0, bl1;
                ldm2(bh0, bh1, a);
                ldm2(bl0, bl1, a + 8192);
                mmaf(ar[ntl], Ar, bh0, bh1); mmaf(az[ntl], Az, bh0, bh1); mmaf(ai[ntl], Ai, bh0, bh1);
                mmaf(ar[ntl], Ar, bl0, bl1); mmaf(az[ntl], Az, bl0, bl1); mmaf(ai[ntl], Ai, bl0, bl1);
            }
        }
        // whh2 @ h2(t-1) (SMEM-resident frags; B from h2rd)
#pragma unroll 2
        for (int kt = 0; kt < 8; kt++) {
            uint4 Ar = wf2[(wpair * 8 + kt) * 32 + lane];
            uint4 Az = wf2[((8 + wpair) * 8 + kt) * 32 + lane];
            uint4 An = wf2[((16 + wpair) * 8 + kt) * 32 + lane];
            uint32_t kb = (uint32_t)((kt * 32 + lh * 16) ^ xorv);
#pragma unroll
            for (int ntl = 0; ntl < 2; ntl++) {
                int nt = ntb + ntl;
                uint32_t a = sb + h2rd + (nt * 8 + lr) * 256 + kb;
                uint32_t bh0, bh1, bl0, bl1;
                ldm2(bh0, bh1, a);
                ldm2(bl0, bl1, a + 8192);
                mmaf(ar[ntl], Ar, bh0, bh1); mmaf(az[ntl], Az, bh0, bh1); mmaf(ah[ntl], An, bh0, bh1);
                mmaf(ar[ntl], Ar, bl0, bl1); mmaf(az[ntl], Az, bl0, bl1); mmaf(ah[ntl], An, bl0, bl1);
            }
        }
        EPILOGUE(b2r, b2z, b2i, b2h, h2reg, h2wr);
        // no barrier here: next-step hazards covered by BARH(t+1) parity walk
        { uint32_t s;
          s = h1rd; h1rd = h1wr; h1wr = s;
          s = h2rd; h2rd = h2wr; h2wr = s;
          s = xrd;  xrd  = xwr;  xwr  = s; }
    }

    // ---- FC head ----
    __syncthreads();                           // full CTA: SMEM reuse below
    float* hs = (float*)smem;                  // [32][128] fp32 over whh2 region
#pragma unroll
    for (int ntl = 0; ntl < 2; ntl++)
#pragma unroll
        for (int e = 0; e < 4; e++) {
            int m = (ntb + ntl) * 8 + tig * 2 + (e & 1);
            int j = wbase + gid + (e >> 1) * 8;
            hs[m * 128 + j] = h2reg[ntl * 4 + e];
        }
    __syncthreads();
    if (tid < 256) {
        int o0 = tid * 3;
#pragma unroll
        for (int o = o0; o < o0 + 3; o++) {
            int m = o / NCLS, c = o - (o / NCLS) * NCLS;
            float acc = fc_b[c];
#pragma unroll 4
            for (int k = 0; k < HID; k++)
                acc = fmaf(fc_w[c * HID + k], hs[m * 128 + k], acc);
            out[(size_t)(b0 + m) * NCLS + c] = acc;
        }
    }
#undef BARH
#undef ZERO_ACC
#undef EPILOGUE
}

// ---------------------------------------------------------------------------
extern "C" void kernel_launch(void* const* d_in, const int* in_sizes, int n_in,
                              void* d_out, int out_size) {
    const float* x     = (const float*)d_in[0];
    const float* w_ih1 = (const float*)d_in[1];
    const float* w_hh1 = (const float*)d_in[2];
    const float* b_ih1 = (const float*)d_in[3];
    const float* b_hh1 = (const float*)d_in[4];
    const float* w_ih2 = (const float*)d_in[5];
    const float* w_hh2 = (const float*)d_in[6];
    const float* b_ih2 = (const float*)d_in[7];
    const float* b_hh2 = (const float*)d_in[8];
    const float* fc_w  = (const float*)d_in[9];
    const float* fc_b  = (const float*)d_in[10];
    float* out = (float*)d_out;

    cudaFuncSetAttribute(gru_mma_kernel,
                         cudaFuncAttributeMaxDynamicSharedMemorySize, SMEM_SZ);

    prep_kernel<<<75, 256>>>(w_ih1, w_hh1, w_ih2, w_hh2);
    gru_mma_kernel<<<4096 / MB, NTHR, SMEM_SZ>>>(x, b_ih1, b_hh1, b_ih2, b_hh2,
                                                 fc_w, fc_b, out);
}

// round 10
// speedup vs baseline: 1.2984x; 1.2984x over previous
#include <cuda_runtime.h>
#include <cuda_fp16.h>
#include <cstdint>

// ---------------------------------------------------------------------------
// GRU via mma.sync (HMMA). 128 CTAs x 512 thr (16 warps), 32 samples/CTA.
// R10: single-fp16 h and x (lo-compensation dropped -> 156 MMA/warp/step,
// was 306). whh1 + whh2 SMEM-resident; only wih2 streams from L2 (merged
// kt loop so LDGs cover SMEM MMAs). Double-buffered h/x, 1 barrier/step.
// Warp (wid&7, wid>>3) owns gate rows 16*(wid&7), samples 16*(wid>>3)..+15.
// ---------------------------------------------------------------------------

#define HID  128
#define MB   32
#define LSEQ 128
#define NCLS 24
#define NTHR 512

// A-fragment arrays: [frag][lane] uint4, frag = mt*nkt + kt
__device__ uint4 g_wih1H[24 * 32], g_wih1L[24 * 32];   // K=16
__device__ uint4 g_whh1H[192 * 32];                    // -> SMEM resident
__device__ uint4 g_wih2H[192 * 32];                    // streamed from L2
__device__ uint4 g_whh2H[192 * 32];                    // -> SMEM resident

// SMEM byte offsets
#define S_WHH1  0        // whh1 hi frags (98304)
#define S_WHH2  98304    // whh2 hi frags (98304)
#define S_H1    196608   // 2 bufs x 8192 (32x128 fp16, swizzled)
#define S_H2    212992   // 2 bufs x 8192
#define S_X     229376   // 2 bufs x 1024 (32x16 fp16)
#define SMEM_SZ 231424

__device__ __forceinline__ uint32_t smem_u32(const void* p) {
    uint32_t a;
    asm("{ .reg .u64 t; cvta.to.shared.u64 t, %1; cvt.u32.u64 %0, t; }"
        : "=r"(a) : "l"(p));
    return a;
}
__device__ __forceinline__ void ldm2(uint32_t& r0, uint32_t& r1, uint32_t a) {
    asm volatile("ldmatrix.sync.aligned.m8n8.x2.shared.b16 {%0,%1}, [%2];"
                 : "=r"(r0), "=r"(r1) : "r"(a));
}
__device__ __forceinline__ void mmaf(float* d, const uint4& a,
                                     uint32_t b0, uint32_t b1) {
    asm volatile("mma.sync.aligned.m16n8k16.row.col.f32.f16.f16.f32 "
                 "{%0,%1,%2,%3}, {%4,%5,%6,%7}, {%8,%9}, {%0,%1,%2,%3};"
                 : "+f"(d[0]), "+f"(d[1]), "+f"(d[2]), "+f"(d[3])
                 : "r"(a.x), "r"(a.y), "r"(a.z), "r"(a.w), "r"(b0), "r"(b1));
}
__device__ __forceinline__ float sigf(float v) { return 1.f / (1.f + __expf(-v)); }
__device__ __forceinline__ float tanhf_fast(float v) {
    v = fminf(fmaxf(v, -15.f), 15.f);
    float e = __expf(2.f * v);
    return (e - 1.f) / (e + 1.f);
}

// ---- prep: pack fp32 weights into per-lane A fragments --------------------
__global__ void prep_kernel(const float* __restrict__ w_ih1,
                            const float* __restrict__ w_hh1,
                            const float* __restrict__ w_ih2,
                            const float* __restrict__ w_hh2) {
    int t = blockIdx.x * blockDim.x + threadIdx.x;
    if (t >= 600 * 32) return;
    int f = t >> 5, lane = t & 31;
    const float* W; uint4* dh; uint4* dl = nullptr; int K, fl;
    if (f < 24)       { W = w_ih1; dh = g_wih1H; dl = g_wih1L; K = 16;  fl = f; }
    else if (f < 216) { W = w_hh1; dh = g_whh1H; K = 128; fl = f - 24; }
    else if (f < 408) { W = w_ih2; dh = g_wih2H; K = 128; fl = f - 216; }
    else              { W = w_hh2; dh = g_whh2H; K = 128; fl = f - 408; }
    int nkt = K >> 4;
    int mt = fl / nkt, kt = fl % nkt;
    int gid = lane >> 2, tig = lane & 3;
    int r0 = mt * 16 + gid, r1 = r0 + 8, c0 = kt * 16 + tig * 2;
    float2 v[4];
    v[0] = *(const float2*)(W + r0 * K + c0);
    v[1] = *(const float2*)(W + r1 * K + c0);
    v[2] = *(const float2*)(W + r0 * K + c0 + 8);
    v[3] = *(const float2*)(W + r1 * K + c0 + 8);
    uint4 oh, ol;
    uint32_t* ph = (uint32_t*)&oh;
    uint32_t* pl = (uint32_t*)&ol;
#pragma unroll
    for (int q = 0; q < 4; q++) {
        __half2 hi = __floats2half2_rn(v[q].x, v[q].y);
        __half2 lo = __floats2half2_rn(v[q].x - __half2float(__low2half(hi)),
                                       v[q].y - __half2float(__high2half(hi)));
        ph[q] = *(uint32_t*)&hi;
        pl[q] = *(uint32_t*)&lo;
    }
    dh[fl * 32 + lane] = oh;
    if (dl) dl[fl * 32 + lane] = ol;
}

// ---------------------------------------------------------------------------
__global__ __launch_bounds__(NTHR, 1)
void gru_mma_kernel(const float* __restrict__ x,
                    const float* __restrict__ b_ih1, const float* __restrict__ b_hh1,
                    const float* __restrict__ b_ih2, const float* __restrict__ b_hh2,
                    const float* __restrict__ fc_w,  const float* __restrict__ fc_b,
                    float* __restrict__ out) {
    extern __shared__ char smem[];
    const uint32_t sb = smem_u32(smem);
    const int tid = threadIdx.x;
    const int wid = tid >> 5, lane = tid & 31;
    const int wpair = wid & 7;           // gate row-group (rows 16*wpair)
    const int shalf = wid >> 3;          // sample half
    const int b0 = blockIdx.x * MB;
    const int gid = lane >> 2, tig = lane & 3;
    const int lr = lane & 7, lh = (lane >> 3) & 1;
    const int xorv = lr << 4;
    const int wbase = wpair * 16;
    const int ntb = shalf * 2;           // this warp's two n-tiles
    const int barid = 1 + shalf;
    const int ht = tid & 255;

#define BARH() asm volatile("bar.sync %0, 256;" :: "r"(barid) : "memory")

    // double-buffer byte offsets
    uint32_t h1rd = S_H1 + 8192, h1wr = S_H1;
    uint32_t h2rd = S_H2 + 8192, h2wr = S_H2;
    uint32_t xrd  = S_X,         xwr  = S_X + 1024;

    // ---- init: whh1 + whh2 frags -> SMEM, zero h buffers, stage x(0) ----
    {
        uint4* d1 = (uint4*)(smem + S_WHH1);
        uint4* d2 = (uint4*)(smem + S_WHH2);
        for (int i = tid; i < 192 * 32; i += NTHR) {
            d1[i] = g_whh1H[i];
            d2[i] = g_whh2H[i];
        }
        uint4 z4 = make_uint4(0, 0, 0, 0);
        uint4* hz = (uint4*)(smem + S_H1);
        for (int i = tid; i < 32768 / 16; i += NTHR) hz[i] = z4;
    }
    if (tid < 256) {
        int m = tid >> 3, p = tid & 7;
        const float2 v = *(const float2*)(x + (size_t)(b0 + m) * 2048 +
                                          (p >> 2) * 1024 + ((2 * p) & 7));
        *(__half2*)(smem + S_X + m * 32 + p * 4) = __floats2half2_rn(v.x, v.y);
    }
    const int j0 = wbase + gid, j1 = j0 + 8;
    float b1r[2] = { b_ih1[j0] + b_hh1[j0],             b_ih1[j1] + b_hh1[j1] };
    float b1z[2] = { b_ih1[128 + j0] + b_hh1[128 + j0], b_ih1[128 + j1] + b_hh1[128 + j1] };
    float b1i[2] = { b_ih1[256 + j0],                   b_ih1[256 + j1] };
    float b1h[2] = { b_hh1[256 + j0],                   b_hh1[256 + j1] };
    float b2r[2] = { b_ih2[j0] + b_hh2[j0],             b_ih2[j1] + b_hh2[j1] };
    float b2z[2] = { b_ih2[128 + j0] + b_hh2[128 + j0], b_ih2[128 + j1] + b_hh2[128 + j1] };
    float b2i[2] = { b_ih2[256 + j0],                   b_ih2[256 + j1] };
    float b2h[2] = { b_hh2[256 + j0],                   b_hh2[256 + j1] };

    float h1reg[8], h2reg[8];
#pragma unroll
    for (int q = 0; q < 8; q++) { h1reg[q] = 0.f; h2reg[q] = 0.f; }

    float ar[2][4], az[2][4], ai[2][4], ah[2][4];
    __syncthreads();

#define ZERO_ACC() { _Pragma("unroll") for (int n_ = 0; n_ < 2; n_++) \
    _Pragma("unroll") for (int e_ = 0; e_ < 4; e_++) { \
        ar[n_][e_] = 0.f; az[n_][e_] = 0.f; ai[n_][e_] = 0.f; ah[n_][e_] = 0.f; } }

// epilogue: gate math + h update + fp16 store to hwr_ (warp-local)
#define EPILOGUE(br_, bz_, bi_, bh_, hreg_, hwr_) { \
    _Pragma("unroll") for (int ntl = 0; ntl < 2; ntl++) { \
        int nt_ = ntb + ntl; \
        _Pragma("unroll") for (int e_ = 0; e_ < 4; e_++) { \
            int rowi_ = e_ >> 1; \
            int m_ = nt_ * 8 + tig * 2 + (e_ & 1); \
            float r_ = sigf(ar[ntl][e_] + br_[rowi_]); \
            float z_ = sigf(az[ntl][e_] + bz_[rowi_]); \
            float n_ = tanhf_fast(ai[ntl][e_] + bi_[rowi_] + r_ * (ah[ntl][e_] + bh_[rowi_])); \
            int idx_ = ntl * 4 + e_; \
            float h_ = n_ + z_ * (hreg_[idx_] - n_); \
            hreg_[idx_] = h_; \
            int j_ = wbase + gid + rowi_ * 8; \
            uint32_t off_ = (hwr_) + m_ * 256 + ((2 * j_) ^ ((m_ & 7) << 4)); \
            *(__half*)(smem + off_) = __float2half_rn(h_); \
        } } }

    const uint4* wf1 = (const uint4*)(smem + S_WHH1);
    const uint4* wf2 = (const uint4*)(smem + S_WHH2);

#pragma unroll 1
    for (int t = 0; t < LSEQ; t++) {
        ZERO_ACC();
        // ---- L1: x contribution (K=16: Whi*x + Wlo*x, x single fp16) ----
        {
            uint4 Ar = g_wih1H[wpair * 32 + lane];
            uint4 Az = g_wih1H[(8 + wpair) * 32 + lane];
            uint4 Ai = g_wih1H[(16 + wpair) * 32 + lane];
            uint4 Lr = g_wih1L[wpair * 32 + lane];
            uint4 Lz = g_wih1L[(8 + wpair) * 32 + lane];
            uint4 Li = g_wih1L[(16 + wpair) * 32 + lane];
#pragma unroll
            for (int ntl = 0; ntl < 2; ntl++) {
                int nt = ntb + ntl;
                uint32_t a = sb + xrd + (nt * 8 + lr) * 32 + lh * 16;
                uint32_t bh0, bh1;
                ldm2(bh0, bh1, a);
                mmaf(ar[ntl], Ar, bh0, bh1); mmaf(az[ntl], Az, bh0, bh1); mmaf(ai[ntl], Ai, bh0, bh1);
                mmaf(ar[ntl], Lr, bh0, bh1); mmaf(az[ntl], Lz, bh0, bh1); mmaf(ai[ntl], Li, bh0, bh1);
            }
        }
        // ---- L1: whh1 @ h1(t-1) (SMEM-resident frags; B from h1rd) ----
#pragma unroll 2
        for (int kt = 0; kt < 8; kt++) {
            uint4 Ar = wf1[(wpair * 8 + kt) * 32 + lane];
            uint4 Az = wf1[((8 + wpair) * 8 + kt) * 32 + lane];
            uint4 An = wf1[((16 + wpair) * 8 + kt) * 32 + lane];
            uint32_t kb = (uint32_t)((kt * 32 + lh * 16) ^ xorv);
#pragma unroll
            for (int ntl = 0; ntl < 2; ntl++) {
                int nt = ntb + ntl;
                uint32_t a = sb + h1rd + (nt * 8 + lr) * 256 + kb;
                uint32_t bh0, bh1;
                ldm2(bh0, bh1, a);
                mmaf(ar[ntl], Ar, bh0, bh1); mmaf(az[ntl], Az, bh0, bh1); mmaf(ah[ntl], An, bh0, bh1);
            }
        }
        EPILOGUE(b1r, b1z, b1i, b1h, h1reg, h1wr);
        if (ht < 128 && t + 1 < LSEQ) {        // stage x(t+1) -> xwr (own half)
            int m = shalf * 16 + (ht >> 3), p = ht & 7;
            const float2 v = *(const float2*)(x + (size_t)(b0 + m) * 2048 +
                                              (p >> 2) * 1024 + (t + 1) * 8 + ((2 * p) & 7));
            *(__half2*)(smem + xwr + m * 32 + p * 4) = __floats2half2_rn(v.x, v.y);
        }
        BARH();   // h1(t) visible to own half; rest covered by buffer parity

        // ---- L2: merged kt loop — wih2 LDGs issue ahead of whh2 SMEM MMAs --
        ZERO_ACC();
#pragma unroll 2
        for (int kt = 0; kt < 8; kt++) {
            // start L2-stream loads first (cover with SMEM work below)
            uint4 Br = g_wih2H[(wpair * 8 + kt) * 32 + lane];
            uint4 Bz = g_wih2H[((8 + wpair) * 8 + kt) * 32 + lane];
            uint4 Bi = g_wih2H[((16 + wpair) * 8 + kt) * 32 + lane];
            // whh2 @ h2(t-1) (SMEM frags)
            uint4 Cr = wf2[(wpair * 8 + kt) * 32 + lane];
            uint4 Cz = wf2[((8 + wpair) * 8 + kt) * 32 + lane];
            uint4 Cn = wf2[((16 + wpair) * 8 + kt) * 32 + lane];
            uint32_t kb = (uint32_t)((kt * 32 + lh * 16) ^ xorv);
#pragma unroll
            for (int ntl = 0; ntl < 2; ntl++) {
                int nt = ntb + ntl;
                uint32_t a2 = sb + h2rd + (nt * 8 + lr) * 256 + kb;
                uint32_t c0, c1;
                ldm2(c0, c1, a2);
                mmaf(ar[ntl], Cr, c0, c1); mmaf(az[ntl], Cz, c0, c1); mmaf(ah[ntl], Cn, c0, c1);
                uint32_t a1 = sb + h1wr + (nt * 8 + lr) * 256 + kb;
                uint32_t d0, d1;
                ldm2(d0, d1, a1);
                mmaf(ar[ntl], Br, d0, d1); mmaf(az[ntl], Bz, d0, d1); mmaf(ai[ntl], Bi, d0, d1);
            }
        }
        EPILOGUE(b2r, b2z, b2i, b2h, h2reg, h2wr);
        { uint32_t s;
          s = h1rd; h1rd = h1wr; h1wr = s;
          s = h2rd; h2rd = h2wr; h2wr = s;
          s = xrd;  xrd  = xwr;  xwr  = s; }
    }

    // ---- FC head ----
    __syncthreads();
    float* hs = (float*)smem;                  // [32][128] fp32 over weight region
#pragma unroll
    for (int ntl = 0; ntl < 2; ntl++)
#pragma unroll
        for (int e = 0; e < 4; e++) {
            int m = (ntb + ntl) * 8 + tig * 2 + (e & 1);
            int j = wbase + gid + (e >> 1) * 8;
            hs[m * 128 + j] = h2reg[ntl * 4 + e];
        }
    __syncthreads();
    if (tid < 256) {
        int o0 = tid * 3;
#pragma unroll
        for (int o = o0; o < o0 + 3; o++) {
            int m = o / NCLS, c = o - (o / NCLS) * NCLS;
            float acc = fc_b[c];
#pragma unroll 4
            for (int k = 0; k < HID; k++)
                acc = fmaf(fc_w[c * HID + k], hs[m * 128 + k], acc);
            out[(size_t)(b0 + m) * NCLS + c] = acc;
        }
    }
#undef BARH
#undef ZERO_ACC
#undef EPILOGUE
}

// ---------------------------------------------------------------------------
extern "C" void kernel_launch(void* const* d_in, const int* in_sizes, int n_in,
                              void* d_out, int out_size) {
    const float* x     = (const float*)d_in[0];
    const float* w_ih1 = (const float*)d_in[1];
    const float* w_hh1 = (const float*)d_in[2];
    const float* b_ih1 = (const float*)d_in[3];
    const float* b_hh1 = (const float*)d_in[4];
    const float* w_ih2 = (const float*)d_in[5];
    const float* w_hh2 = (const float*)d_in[6];
    const float* b_ih2 = (const float*)d_in[7];
    const float* b_hh2 = (const float*)d_in[8];
    const float* fc_w  = (const float*)d_in[9];
    const float* fc_b  = (const float*)d_in[10];
    float* out = (float*)d_out;

    cudaFuncSetAttribute(gru_mma_kernel,
                         cudaFuncAttributeMaxDynamicSharedMemorySize, SMEM_SZ);

    prep_kernel<<<75, 256>>>(w_ih1, w_hh1, w_ih2, w_hh2);
    gru_mma_kernel<<<4096 / MB, NTHR, SMEM_SZ>>>(x, b_ih1, b_hh1, b_ih2, b_hh2,
                                                 fc_w, fc_b, out);
}